// round 9
// baseline (speedup 1.0000x reference)
#include <cuda_runtime.h>
#include <cuda_bf16.h>
#include <math.h>
#include <stdint.h>

#define Bb 32
#define Ss 24
#define Tt 24
#define Vv 30000
#define Ee 620
#define Hh 1000
#define Mm 500
#define RS (Ss*Bb)   /* 768 */
#define RT (Tt*Bb)   /* 768 */
#define NBLK 125
#define NCOLS 8

#define K3E 1920   /* 3*620=1860 -> pad 1920 */
#define K3H 3072   /* 3*1000=3000 -> pad 3072 */
#define K3M 1536   /* 3*500=1500 -> pad 1536 */

// ---------------- fp32 scratch ----------------
__device__ float g_Xr[RS*Hh];    // [t][j][b]
__device__ float g_Xz[RS*Hh];
__device__ float g_Xc[RS*Hh];
__device__ float g_Yr[RT*Hh];
__device__ float g_Yz[RT*Hh];
__device__ float g_Yc[RT*Hh];
__device__ float g_Yo[RT*Hh];    // normal [row][2M]
__device__ float g_hT2[Hh*Bb];   // paired transposed state
__device__ float g_s0T[Hh*Bb];
__device__ float g_rhT2[Hh*Bb];
__device__ float g_cCrT[Hh*Bb];
__device__ float g_cCzT[Hh*Bb];
__device__ float g_cCT [Hh*Bb];
__device__ float g_cCo[Bb*Hh];
__device__ unsigned g_arrive[128];
__device__ unsigned g_go;

// ---------------- bf16 tripled operands ----------------
__device__ __nv_bfloat16 g3_eWr[Hh*K3E];
__device__ __nv_bfloat16 g3_eWz[Hh*K3E];
__device__ __nv_bfloat16 g3_eW [Hh*K3E];
__device__ __nv_bfloat16 g3_dWr[Hh*K3E];
__device__ __nv_bfloat16 g3_dWz[Hh*K3E];
__device__ __nv_bfloat16 g3_dW [Hh*K3E];
__device__ __nv_bfloat16 g3_Vo [Hh*K3E];
__device__ __nv_bfloat16 g3_Ws [Hh*K3H];
__device__ __nv_bfloat16 g3_Cr [Hh*K3H];
__device__ __nv_bfloat16 g3_Cz [Hh*K3H];
__device__ __nv_bfloat16 g3_C  [Hh*K3H];
__device__ __nv_bfloat16 g3_Co [Hh*K3H];
__device__ __nv_bfloat16 g3_Uo [Hh*K3H];
__device__ __nv_bfloat16 g3_Wo [Vv*K3M];
__device__ __nv_bfloat16 g3_X  [RS*K3E];
__device__ __nv_bfloat16 g3_Y  [RT*K3E];
__device__ __nv_bfloat16 g3_cT [Bb*K3H];
__device__ __nv_bfloat16 g3_S  [RT*K3H];   // tripled decoder pre-update states
__device__ __nv_bfloat16 g3_T  [RT*K3M];   // tripled maxout output

__device__ __forceinline__ int ptidx(int j, int b) { return ((j >> 1) * 64) + 2 * b + (j & 1); }

// ---------------- embedding gather fused with bf16 tripling (A layout: hi|lo|hi) ----------------
__global__ void gather_trip(const int* __restrict__ tok, const float* __restrict__ emb,
                            __nv_bfloat16* __restrict__ out3, int L)
{
    int r = blockIdx.x;
    int s = r >> 5, b = r & 31;
    int token = tok[b * L + s];
    const float* srcp = emb + (long)token * Ee;
    __nv_bfloat16* dst = out3 + (size_t)r * K3E;
    for (int e = threadIdx.x; e < Ee; e += blockDim.x) {
        float v = srcp[e];
        __nv_bfloat16 h = __float2bfloat16(v);
        __nv_bfloat16 l = __float2bfloat16(v - __bfloat162float(h));
        dst[e] = h; dst[Ee + e] = l; dst[2 * Ee + e] = h;
    }
    // pad region [3*Ee, K3E) stays zero (zero-initialized device global, never written)
}

// ---------------- fp32 -> tripled bf16 convert (weights / ctx) ----------------
// typeB=1 (B operand): [hi | hi | lo];  typeB=0 (A operand): [hi | lo | hi]
struct ConvEntry { const float* src; __nv_bfloat16* dst; int R, K, K3p, typeB, paired; };
struct ConvBatch { ConvEntry e[8]; };

__global__ void conv_k(ConvBatch cb)
{
    ConvEntry E = cb.e[blockIdx.y];
    int per = E.K3p >> 3;
    int total = E.R * per;
    int i = blockIdx.x * 256 + threadIdx.x;
    if (i >= total) return;
    int r = i / per, c8 = (i - r * per) * 8;
    const float* s = E.src + (size_t)r * E.K;
    __nv_bfloat16 o[8];
#pragma unroll
    for (int j = 0; j < 8; j++) {
        int k3 = c8 + j;
        int K = E.K;
        float v = 0.f; int wantLo = 0;
        int k = -1;
        if (k3 < K)          { k = k3;         wantLo = 0; }
        else if (k3 < 2 * K) { k = k3 - K;     wantLo = E.typeB ? 0 : 1; }
        else if (k3 < 3 * K) { k = k3 - 2 * K; wantLo = E.typeB ? 1 : 0; }
        if (k >= 0) v = E.paired ? E.src[((k >> 1) << 6) + 2 * r + (k & 1)] : s[k];
        __nv_bfloat16 h = __float2bfloat16(v);
        o[j] = wantLo ? __float2bfloat16(v - __bfloat162float(h)) : h;
    }
    *(float4*)(E.dst + (size_t)r * E.K3p + c8) = *(float4*)o;
}

// ================= bf16 GEMM (cp.async double-buffered) =================
// modes: 0: C[row*ldc+col] (+bias)
//        3: logits scatter C[(row&31)*T*V + (row>>5)*V + col]
//        4: trans-flat C[((row>>5)*Hh + col)*32 + (row&31)] (+bias)
//        5: dual tanh: add1[ptidx(col,row&31)]=tanh(v); C=S3 tripled row (row&31)
//        6: maxout-fused: v=acc+add1+add2; pairwise max; C=T3 tripled
struct MultiGemm {
    const __nv_bfloat16* A3;
    const __nv_bfloat16* B3[5];
    void*        C[5];
    const float* bias[5];
    const float* add1[5];
    const float* add2[5];
    int mode[5];
    int M, N, K3p, ldc;
};

#define GBM 128
#define GBN 128
#define GBK 64
#define GSK 72
#define GSTAGE_ELEMS (128*GSK)
#define GSMEM_BYTES (4*GSTAGE_ELEMS*2)

__device__ __forceinline__ uint32_t smem_u32(const void* p) {
    return (uint32_t)__cvta_generic_to_shared(p);
}
__device__ __forceinline__ void ldsm4(uint32_t &r0, uint32_t &r1, uint32_t &r2, uint32_t &r3, uint32_t a) {
    asm volatile("ldmatrix.sync.aligned.m8n8.x4.shared.b16 {%0,%1,%2,%3}, [%4];\n"
        : "=r"(r0), "=r"(r1), "=r"(r2), "=r"(r3) : "r"(a));
}
__device__ __forceinline__ void mma_bf16(float* c, const uint32_t* a, uint32_t b0, uint32_t b1) {
    asm volatile("mma.sync.aligned.m16n8k16.row.col.f32.bf16.bf16.f32 "
        "{%0,%1,%2,%3},{%4,%5,%6,%7},{%8,%9},{%0,%1,%2,%3};\n"
        : "+f"(c[0]), "+f"(c[1]), "+f"(c[2]), "+f"(c[3])
        : "r"(a[0]), "r"(a[1]), "r"(a[2]), "r"(a[3]), "r"(b0), "r"(b1));
}
__device__ __forceinline__ void cpasync16(uint32_t daddr, const void* src, int sbytes) {
    asm volatile("cp.async.cg.shared.global [%0], [%1], 16, %2;\n"
        :: "r"(daddr), "l"(src), "r"(sbytes));
}

__global__ __launch_bounds__(256, 2)
void bf16_gemm(MultiGemm g)
{
    extern __shared__ __nv_bfloat16 smem[];
    __nv_bfloat16* sA = smem;
    __nv_bfloat16* sB = smem + 2 * GSTAGE_ELEMS;

    int z = blockIdx.z;
    const __nv_bfloat16* A  = g.A3;
    const __nv_bfloat16* Bm = g.B3[z];
    void* C           = g.C[z];
    const float* bias = g.bias[z];
    const float* add1 = g.add1[z];
    const float* add2 = g.add2[z];
    int mode = g.mode[z];
    int M = g.M, N = g.N, K3p = g.K3p, ldc = g.ldc;

    int t = threadIdx.x, lane = t & 31, wid = t >> 5;
    int wm = wid & 1, wn = wid >> 1;
    int m0 = blockIdx.y * GBM, n0 = blockIdx.x * GBN;

    float acc[4][4][4];
#pragma unroll
    for (int i = 0; i < 4; i++)
#pragma unroll
        for (int j = 0; j < 4; j++)
#pragma unroll
            for (int c = 0; c < 4; c++) acc[i][j][c] = 0.f;

    int sel = lane >> 3, l7 = lane & 7;
    int ar = (sel & 1) * 8 + l7;
    int ac = (sel >> 1) * 8;
    int br = (sel >> 1) * 8 + l7;
    int bc = (sel & 1) * 8;

    int KT = K3p / GBK;

    auto loadStage = [&](int kt, int st) {
        int kbase = kt * GBK;
#pragma unroll
        for (int i = 0; i < 4; i++) {
            int idx = t + i * 256;
            int row = idx >> 3, sg = idx & 7;
            {
                int gr = m0 + row;
                int ok = (gr < M);
                const __nv_bfloat16* src = A + (size_t)(ok ? gr : 0) * K3p + kbase + sg * 8;
                cpasync16(smem_u32(&sA[st * GSTAGE_ELEMS + row * GSK + sg * 8]), src, ok ? 16 : 0);
            }
            {
                int gr = n0 + row;
                int ok = (gr < N);
                const __nv_bfloat16* src = Bm + (size_t)(ok ? gr : 0) * K3p + kbase + sg * 8;
                cpasync16(smem_u32(&sB[st * GSTAGE_ELEMS + row * GSK + sg * 8]), src, ok ? 16 : 0);
            }
        }
        asm volatile("cp.async.commit_group;\n");
    };

    loadStage(0, 0);

    for (int kt = 0; kt < KT; kt++) {
        int st = kt & 1;
        if (kt + 1 < KT) {
            loadStage(kt + 1, st ^ 1);
            asm volatile("cp.async.wait_group 1;\n");
        } else {
            asm volatile("cp.async.wait_group 0;\n");
        }
        __syncthreads();

        const __nv_bfloat16* a_st = sA + st * GSTAGE_ELEMS;
        const __nv_bfloat16* b_st = sB + st * GSTAGE_ELEMS;
#pragma unroll
        for (int kh = 0; kh < 4; kh++) {
            uint32_t af[4][4], bf[4][2];
#pragma unroll
            for (int mi = 0; mi < 4; mi++) {
                uint32_t addr = smem_u32(&a_st[(wm * 64 + mi * 16 + ar) * GSK + kh * 16 + ac]);
                ldsm4(af[mi][0], af[mi][1], af[mi][2], af[mi][3], addr);
            }
#pragma unroll
            for (int p = 0; p < 2; p++) {
                uint32_t r0, r1, r2, r3;
                uint32_t addr = smem_u32(&b_st[(wn * 32 + p * 16 + br) * GSK + kh * 16 + bc]);
                ldsm4(r0, r1, r2, r3, addr);
                bf[2*p][0] = r0; bf[2*p][1] = r1; bf[2*p+1][0] = r2; bf[2*p+1][1] = r3;
            }
#pragma unroll
            for (int mi = 0; mi < 4; mi++)
#pragma unroll
                for (int ni = 0; ni < 4; ni++)
                    mma_bf16(acc[mi][ni], af[mi], bf[ni][0], bf[ni][1]);
        }
        __syncthreads();
    }

    int gq = lane >> 2, tig = lane & 3;
    if (mode == 6) {
        // maxout-fused: pairwise max of adjacent cols, write tripled bf16 T3
        __nv_bfloat16* T = (__nv_bfloat16*)C;
#pragma unroll
        for (int mi = 0; mi < 4; mi++) {
#pragma unroll
            for (int ni = 0; ni < 4; ni++) {
                int colb = n0 + wn * 32 + ni * 8 + tig * 2;
                if (colb >= N) continue;
                int m = colb >> 1;
#pragma unroll
                for (int half = 0; half < 2; half++) {
                    int row = m0 + wm * 64 + mi * 16 + gq + half * 8;
                    if (row >= M) continue;
                    int b = row & 31;
                    float v0 = acc[mi][ni][half * 2 + 0] + add1[(size_t)row * ldc + colb]     + add2[(size_t)b * ldc + colb];
                    float v1 = acc[mi][ni][half * 2 + 1] + add1[(size_t)row * ldc + colb + 1] + add2[(size_t)b * ldc + colb + 1];
                    float vm = fmaxf(v0, v1);
                    __nv_bfloat16 h = __float2bfloat16(vm);
                    __nv_bfloat16 l = __float2bfloat16(vm - __bfloat162float(h));
                    size_t base = (size_t)row * K3M;
                    T[base + m] = h; T[base + Mm + m] = l; T[base + 2 * Mm + m] = h;
                }
            }
        }
        return;
    }
#pragma unroll
    for (int mi = 0; mi < 4; mi++) {
#pragma unroll
        for (int ni = 0; ni < 4; ni++) {
#pragma unroll
            for (int c = 0; c < 4; c++) {
                int row = m0 + wm * 64 + mi * 16 + gq + ((c >> 1) ? 8 : 0);
                int col = n0 + wn * 32 + ni * 8 + tig * 2 + (c & 1);
                if (row >= M || col >= N) continue;
                float v = acc[mi][ni][c];
                if (mode == 0) {
                    if (bias) v += bias[col];
                    ((float*)C)[(size_t)row * ldc + col] = v;
                } else if (mode == 3) {
                    int b = row & 31, ti = row >> 5;
                    ((float*)C)[(size_t)b * (Tt * Vv) + (size_t)ti * Vv + col] = v;
                } else if (mode == 4) {
                    if (bias) v += bias[col];
                    int b = row & 31, ti = row >> 5;
                    ((float*)C)[((size_t)ti * Hh + col) * 32 + b] = v;
                } else { // 5: tanh -> s0T paired + S3 tripled row b
                    int b = row & 31;
                    float tv = tanhf(v);
                    ((float*)add1)[ptidx(col, b)] = tv;
                    __nv_bfloat16 h = __float2bfloat16(tv);
                    __nv_bfloat16 l = __float2bfloat16(tv - __bfloat162float(h));
                    __nv_bfloat16* S3p = (__nv_bfloat16*)C;
                    size_t base = (size_t)b * K3H;
                    S3p[base + col] = h; S3p[base + Hh + col] = l; S3p[base + 2 * Hh + col] = h;
                }
            }
        }
    }
}

// ================= persistent recurrence =================
__device__ __forceinline__ unsigned long long pack2(float2 v) {
    unsigned long long r;
    asm("mov.b64 %0, {%1, %2};" : "=l"(r) : "f"(v.x), "f"(v.y));
    return r;
}
__device__ __forceinline__ unsigned long long pack2f(float a, float b) {
    unsigned long long r;
    asm("mov.b64 %0, {%1, %2};" : "=l"(r) : "f"(a), "f"(b));
    return r;
}
__device__ __forceinline__ float2 unpack2(unsigned long long v) {
    float2 r;
    asm("mov.b64 {%0, %1}, %2;" : "=f"(r.x), "=f"(r.y) : "l"(v));
    return r;
}
__device__ __forceinline__ void ffma2(unsigned long long &acc, unsigned long long a, unsigned long long b) {
    asm("fma.rn.f32x2 %0, %1, %2, %0;" : "+l"(acc) : "l"(a), "l"(b));
}

// fast flag-array grid barrier: parallel arrivals + block-0 aggregation + go epoch
__device__ __forceinline__ void gbar2(unsigned epoch) {
    __syncthreads();
    __threadfence();
    int tid = threadIdx.x, bid = blockIdx.x;
    if (tid == 0)
        asm volatile("st.relaxed.gpu.global.u32 [%0], %1;" :: "l"(&g_arrive[bid]), "r"(epoch) : "memory");
    if (bid == 0) {
        if (tid < NBLK) {
            unsigned v;
            do {
                asm volatile("ld.relaxed.gpu.global.u32 %0, [%1];" : "=r"(v) : "l"(&g_arrive[tid]) : "memory");
            } while (v < epoch);
        }
        __syncthreads();
        __threadfence();
        if (tid == 0)
            asm volatile("st.relaxed.gpu.global.u32 [%0], %1;" :: "l"(&g_go), "r"(epoch) : "memory");
    }
    if (tid == 0) {
        unsigned v;
        do {
            asm volatile("ld.relaxed.gpu.global.u32 %0, [%1];" : "=r"(v) : "l"(&g_go) : "memory");
        } while (v < epoch);
    }
    __syncthreads();
    __threadfence();
}

#define SMEM_RECUR (28352*4)

__global__ __launch_bounds__(256, 1)
void recur_persist(float* __restrict__ hT2, float* __restrict__ rhT2,
    const float* __restrict__ GUr, const float* __restrict__ GUz, const float* __restrict__ GUc,
    const float* __restrict__ Xr, const float* __restrict__ Xz, const float* __restrict__ Xc,
    const float* __restrict__ ctxR, const float* __restrict__ ctxZ, const float* __restrict__ ctxC,
    __nv_bfloat16* __restrict__ S3out, int nsteps)
{
    extern __shared__ float sm[];
    float* usr = sm;
    float* usz = sm + 8000;
    float* usc = sm + 16000;
    float* red = sm + 24000;
    float* zs  = sm + 28096;
    int tid = threadIdx.x, lane = tid & 31, w = tid >> 5;
    int jbase = blockIdx.x * NCOLS;

    for (int i4 = tid; i4 < 2000; i4 += 256) {
        int row = i4 / 250, k4 = (i4 % 250) * 4;
        *(float4*)(usr + row * 1000 + k4) = *(const float4*)(GUr + (size_t)(jbase + row) * 1000 + k4);
        *(float4*)(usz + row * 1000 + k4) = *(const float4*)(GUz + (size_t)(jbase + row) * 1000 + k4);
        *(float4*)(usc + row * 1000 + k4) = *(const float4*)(GUc + (size_t)(jbase + row) * 1000 + k4);
    }
    __syncthreads();

    const int offs[8] = {0, 64, 128, 192, 256, 318, 380, 440};
    const int lens[8] = {64, 64, 64, 64, 62, 62, 60, 60};
    int off = offs[w], len = lens[w];
    unsigned ep = 1;

    for (int step = 0; step < nsteps; step++) {
        // ---------- phase A: r,z gates ----------
        {
            unsigned long long acc[16];
#pragma unroll
            for (int p = 0; p < 16; p++) acc[p] = 0ull;
            float2 h0 = *(const float2*)(hT2 + (off) * 64 + 2 * lane);
            float2 h1 = *(const float2*)(hT2 + (off + 1) * 64 + 2 * lane);
            for (int i = 0; i < len; i += 2) {
                float2 n0, n1;
                if (i + 2 < len) {
                    n0 = *(const float2*)(hT2 + (off + i + 2) * 64 + 2 * lane);
                    n1 = *(const float2*)(hT2 + (off + i + 3) * 64 + 2 * lane);
                }
                int k0 = (off + i) * 2;
                unsigned long long h0p = pack2(h0), h1p = pack2(h1);
#pragma unroll
                for (int p = 0; p < 16; p++) {
                    const float* us = (p & 1) ? usz : usr;
                    float4 u = *(const float4*)(us + (p >> 1) * 1000 + k0);
                    ffma2(acc[p], h0p, pack2f(u.x, u.y));
                    ffma2(acc[p], h1p, pack2f(u.z, u.w));
                }
                h0 = n0; h1 = n1;
            }
#pragma unroll
            for (int p = 0; p < 16; p++) {
                float2 a = unpack2(acc[p]);
                red[w * 512 + p * 32 + lane] = a.x + a.y;
            }
            __syncthreads();
            for (int o = tid; o < 512; o += 256) {
                int p = o >> 5, b = o & 31;
                int col = p >> 1, gate = p & 1;
                int jg = jbase + col;
                float s = 0.f;
#pragma unroll
                for (int ww = 0; ww < 8; ww++) s += red[ww * 512 + p * 32 + b];
                const float* X = gate ? Xz : Xr;
                float pre = X[((size_t)step * Hh + jg) * 32 + b] + s;
                const float* ctx = gate ? ctxZ : ctxR;
                if (ctx) pre += ctx[jg * 32 + b];
                float sg = 1.f / (1.f + __expf(-pre));
                if (gate == 0) {
                    int hi = ptidx(jg, b);
                    rhT2[hi] = sg * hT2[hi];
                } else {
                    zs[col * 32 + b] = sg;
                }
            }
        }
        gbar2(ep++);
        // ---------- phase B: candidate + blend ----------
        {
            unsigned long long acc[8];
#pragma unroll
            for (int p = 0; p < 8; p++) acc[p] = 0ull;
            float2 h0 = *(const float2*)(rhT2 + (off) * 64 + 2 * lane);
            float2 h1 = *(const float2*)(rhT2 + (off + 1) * 64 + 2 * lane);
            for (int i = 0; i < len; i += 2) {
                float2 n0, n1;
                if (i + 2 < len) {
                    n0 = *(const float2*)(rhT2 + (off + i + 2) * 64 + 2 * lane);
                    n1 = *(const float2*)(rhT2 + (off + i + 3) * 64 + 2 * lane);
                }
                int k0 = (off + i) * 2;
                unsigned long long h0p = pack2(h0), h1p = pack2(h1);
#pragma unroll
                for (int p = 0; p < 8; p++) {
                    float4 u = *(const float4*)(usc + p * 1000 + k0);
                    ffma2(acc[p], h0p, pack2f(u.x, u.y));
                    ffma2(acc[p], h1p, pack2f(u.z, u.w));
                }
                h0 = n0; h1 = n1;
            }
            __syncthreads();
#pragma unroll
            for (int p = 0; p < 8; p++) {
                float2 a = unpack2(acc[p]);
                red[w * 256 + p * 32 + lane] = a.x + a.y;
            }
            __syncthreads();
            {
                int col = tid >> 5, b = tid & 31;
                int jg = jbase + col;
                float s = 0.f;
#pragma unroll
                for (int ww = 0; ww < 8; ww++) s += red[ww * 256 + col * 32 + b];
                float pre = Xc[((size_t)step * Hh + jg) * 32 + b] + s;
                if (ctxC) pre += ctxC[jg * 32 + b];
                float cand = tanhf(pre);
                float zv = zs[col * 32 + b];
                int hi = ptidx(jg, b);
                float hv = hT2[hi];
                float hn = (1.f - zv) * hv + zv * cand;
                hT2[hi] = hn;
                if (S3out != nullptr && step + 1 < nsteps) {
                    __nv_bfloat16 h = __float2bfloat16(hn);
                    __nv_bfloat16 l = __float2bfloat16(hn - __bfloat162float(h));
                    size_t base = ((size_t)(step + 1) * 32 + b) * K3H;
                    S3out[base + jg] = h; S3out[base + Hh + jg] = l; S3out[base + 2 * Hh + jg] = h;
                }
            }
        }
        gbar2(ep++);
    }
}

// ---------------- host orchestration ----------------
extern "C" void kernel_launch(void* const* d_in, const int* in_sizes, int n_in,
                              void* d_out, int out_size)
{
    const int*   src     = (const int*)d_in[0];
    const int*   tgt     = (const int*)d_in[1];
    const float* src_emb = (const float*)d_in[3];
    const float* tgt_emb = (const float*)d_in[4];
    const float* enc_W   = (const float*)d_in[5];
    const float* enc_Wz  = (const float*)d_in[6];
    const float* enc_Wr  = (const float*)d_in[7];
    const float* enc_U   = (const float*)d_in[8];
    const float* enc_Uz  = (const float*)d_in[9];
    const float* enc_Ur  = (const float*)d_in[10];
    const float* enc_b   = (const float*)d_in[11];
    const float* enc_bz  = (const float*)d_in[12];
    const float* enc_br  = (const float*)d_in[13];
    const float* dec_W   = (const float*)d_in[14];
    const float* dec_Wz  = (const float*)d_in[15];
    const float* dec_Wr  = (const float*)d_in[16];
    const float* dec_U   = (const float*)d_in[17];
    const float* dec_Uz  = (const float*)d_in[18];
    const float* dec_Ur  = (const float*)d_in[19];
    const float* dec_C   = (const float*)d_in[20];
    const float* dec_Cz  = (const float*)d_in[21];
    const float* dec_Cr  = (const float*)d_in[22];
    const float* dec_b   = (const float*)d_in[23];
    const float* dec_bz  = (const float*)d_in[24];
    const float* dec_br  = (const float*)d_in[25];
    const float* W_s     = (const float*)d_in[26];
    const float* U_o     = (const float*)d_in[27];
    const float* V_o     = (const float*)d_in[28];
    const float* C_o     = (const float*)d_in[29];
    const float* W_o     = (const float*)d_in[30];
    float* out = (float*)d_out;

    float *Xr, *Xz, *Xc, *Yr, *Yz, *Yc, *Yo;
    float *hT2, *s0T, *rhT2, *cCrT, *cCzT, *cCT, *cCo;
    unsigned *arrive, *go;
    cudaGetSymbolAddress((void**)&Xr, g_Xr);
    cudaGetSymbolAddress((void**)&Xz, g_Xz);
    cudaGetSymbolAddress((void**)&Xc, g_Xc);
    cudaGetSymbolAddress((void**)&Yr, g_Yr);
    cudaGetSymbolAddress((void**)&Yz, g_Yz);
    cudaGetSymbolAddress((void**)&Yc, g_Yc);
    cudaGetSymbolAddress((void**)&Yo, g_Yo);
    cudaGetSymbolAddress((void**)&hT2, g_hT2);
    cudaGetSymbolAddress((void**)&s0T, g_s0T);
    cudaGetSymbolAddress((void**)&rhT2, g_rhT2);
    cudaGetSymbolAddress((void**)&cCrT, g_cCrT);
    cudaGetSymbolAddress((void**)&cCzT, g_cCzT);
    cudaGetSymbolAddress((void**)&cCT,  g_cCT);
    cudaGetSymbolAddress((void**)&cCo, g_cCo);
    cudaGetSymbolAddress((void**)&arrive, g_arrive);
    cudaGetSymbolAddress((void**)&go, g_go);

    __nv_bfloat16 *eWr3, *eWz3, *eW3, *dWr3, *dWz3, *dW3, *Vo3;
    __nv_bfloat16 *Ws3, *Cr3, *Cz3, *C3, *Co3, *Uo3, *Wo3;
    __nv_bfloat16 *X3, *Y3, *cT3, *S3, *T3;
    cudaGetSymbolAddress((void**)&eWr3, g3_eWr);
    cudaGetSymbolAddress((void**)&eWz3, g3_eWz);
    cudaGetSymbolAddress((void**)&eW3,  g3_eW);
    cudaGetSymbolAddress((void**)&dWr3, g3_dWr);
    cudaGetSymbolAddress((void**)&dWz3, g3_dWz);
    cudaGetSymbolAddress((void**)&dW3,  g3_dW);
    cudaGetSymbolAddress((void**)&Vo3,  g3_Vo);
    cudaGetSymbolAddress((void**)&Ws3,  g3_Ws);
    cudaGetSymbolAddress((void**)&Cr3,  g3_Cr);
    cudaGetSymbolAddress((void**)&Cz3,  g3_Cz);
    cudaGetSymbolAddress((void**)&C3,   g3_C);
    cudaGetSymbolAddress((void**)&Co3,  g3_Co);
    cudaGetSymbolAddress((void**)&Uo3,  g3_Uo);
    cudaGetSymbolAddress((void**)&Wo3,  g3_Wo);
    cudaGetSymbolAddress((void**)&X3,   g3_X);
    cudaGetSymbolAddress((void**)&Y3,   g3_Y);
    cudaGetSymbolAddress((void**)&cT3,  g3_cT);
    cudaGetSymbolAddress((void**)&S3,   g3_S);
    cudaGetSymbolAddress((void**)&T3,   g3_T);

    cudaFuncSetAttribute(recur_persist, cudaFuncAttributeMaxDynamicSharedMemorySize, SMEM_RECUR);
    cudaFuncSetAttribute(bf16_gemm, cudaFuncAttributeMaxDynamicSharedMemorySize, GSMEM_BYTES);

    // ---- weight converts ----
    {
        ConvBatch cb = {};
        const float* s[7] = {enc_Wr, enc_Wz, enc_W, dec_Wr, dec_Wz, dec_W, V_o};
        __nv_bfloat16* d[7] = {eWr3, eWz3, eW3, dWr3, dWz3, dW3, Vo3};
        for (int i = 0; i < 7; i++) cb.e[i] = {s[i], d[i], Hh, Ee, K3E, 1, 0};
        int total = Hh * (K3E / 8);
        dim3 gr((total + 255) / 256, 7);
        conv_k<<<gr, 256>>>(cb);
    }
    {
        ConvBatch cb = {};
        const float* s[6] = {W_s, dec_Cr, dec_Cz, dec_C, C_o, U_o};
        __nv_bfloat16* d[6] = {Ws3, Cr3, Cz3, C3, Co3, Uo3};
        for (int i = 0; i < 6; i++) cb.e[i] = {s[i], d[i], Hh, Hh, K3H, 1, 0};
        int total = Hh * (K3H / 8);
        dim3 gr((total + 255) / 256, 6);
        conv_k<<<gr, 256>>>(cb);
    }
    {
        ConvBatch cb = {};
        cb.e[0] = {W_o, Wo3, Vv, Mm, K3M, 1, 0};
        int total = Vv * (K3M / 8);
        dim3 gr((total + 255) / 256, 1);
        conv_k<<<gr, 256>>>(cb);
    }

    // ---- fused gathers (emb -> tripled bf16) ----
    gather_trip<<<RS, 128>>>(src, src_emb, X3, Ss);
    gather_trip<<<RT, 128>>>(tgt, tgt_emb, Y3, Tt);

    // ---- input projections ----
    {
        MultiGemm g = {};
        g.A3 = X3; g.M = RS; g.N = Hh; g.K3p = K3E; g.ldc = Hh;
        g.B3[0] = eWr3; g.C[0] = Xr; g.bias[0] = enc_br; g.mode[0] = 4;
        g.B3[1] = eWz3; g.C[1] = Xz; g.bias[1] = enc_bz; g.mode[1] = 4;
        g.B3[2] = eW3;  g.C[2] = Xc; g.bias[2] = enc_b;  g.mode[2] = 4;
        dim3 gr((Hh + GBN - 1) / GBN, (RS + GBM - 1) / GBM, 3);
        bf16_gemm<<<gr, 256, GSMEM_BYTES>>>(g);
    }
    {
        MultiGemm g = {};
        g.A3 = Y3; g.M = RT; g.N = Hh; g.K3p = K3E; g.ldc = Hh;
        g.B3[0] = dWr3; g.C[0] = Yr; g.bias[0] = dec_br; g.mode[0] = 4;
        g.B3[1] = dWz3; g.C[1] = Yz; g.bias[1] = dec_bz; g.mode[1] = 4;
        g.B3[2] = dW3;  g.C[2] = Yc; g.bias[2] = dec_b;  g.mode[2] = 4;
        g.B3[3] = Vo3;  g.C[3] = Yo; g.bias[3] = nullptr; g.mode[3] = 0;
        dim3 gr((Hh + GBN - 1) / GBN, (RT + GBM - 1) / GBM, 4);
        bf16_gemm<<<gr, 256, GSMEM_BYTES>>>(g);
    }

    // ---- encoder recurrence ----
    cudaMemsetAsync(hT2, 0, (size_t)Hh * Bb * sizeof(float));
    cudaMemsetAsync(arrive, 0, 128 * sizeof(unsigned));
    cudaMemsetAsync(go, 0, sizeof(unsigned));
    recur_persist<<<NBLK, 256, SMEM_RECUR>>>(hT2, rhT2,
        enc_Ur, enc_Uz, enc_U, Xr, Xz, Xc,
        nullptr, nullptr, nullptr, nullptr, Ss);

    // ---- context projections ----
    {
        ConvBatch cb = {};
        cb.e[0] = {hT2, cT3, Bb, Hh, K3H, 0, 1};
        int total = Bb * (K3H / 8);
        dim3 gr((total + 255) / 256, 1);
        conv_k<<<gr, 256>>>(cb);
    }
    {
        MultiGemm g = {};
        g.A3 = cT3; g.M = Bb; g.N = Hh; g.K3p = K3H; g.ldc = Hh;
        g.B3[0] = Ws3; g.C[0] = S3;   g.add1[0] = s0T; g.mode[0] = 5;  // tanh -> s0T + S3 row0
        g.B3[1] = Cr3; g.C[1] = cCrT; g.mode[1] = 4;
        g.B3[2] = Cz3; g.C[2] = cCzT; g.mode[2] = 4;
        g.B3[3] = C3;  g.C[3] = cCT;  g.mode[3] = 4;
        g.B3[4] = Co3; g.C[4] = cCo;  g.mode[4] = 0;
        dim3 gr((Hh + GBN - 1) / GBN, 1, 5);
        bf16_gemm<<<gr, 256, GSMEM_BYTES>>>(g);
    }

    // ---- decoder recurrence (writes tripled S3 directly) ----
    cudaMemsetAsync(arrive, 0, 128 * sizeof(unsigned));
    cudaMemsetAsync(go, 0, sizeof(unsigned));
    recur_persist<<<NBLK, 256, SMEM_RECUR>>>(s0T, rhT2,
        dec_Ur, dec_Uz, dec_U, Yr, Yz, Yc,
        cCrT, cCzT, cCT, S3, Tt);

    // ---- output layer: tfull + maxout + tripling fused (mode 6) ----
    {
        MultiGemm g = {};
        g.A3 = S3; g.M = RT; g.N = Hh; g.K3p = K3H; g.ldc = Hh;
        g.B3[0] = Uo3; g.C[0] = T3; g.add1[0] = Yo; g.add2[0] = cCo; g.mode[0] = 6;
        dim3 gr((Hh + GBN - 1) / GBN, (RT + GBM - 1) / GBM, 1);
        bf16_gemm<<<gr, 256, GSMEM_BYTES>>>(g);
    }
    // ---- logits ----
    {
        MultiGemm g = {};
        g.A3 = T3; g.M = RT; g.N = Vv; g.K3p = K3M; g.ldc = Vv;
        g.B3[0] = Wo3; g.C[0] = out; g.mode[0] = 3;
        dim3 gr((Vv + GBN - 1) / GBN, (RT + GBM - 1) / GBM, 1);
        bf16_gemm<<<gr, 256, GSMEM_BYTES>>>(g);
    }
}